// round 14
// baseline (speedup 1.0000x reference)
#include <cuda_runtime.h>
#include <cuda_bf16.h>
#include <cstdint>

// Problem constants (fixed by setup_inputs)
#define BATCH 4
#define MDIM 4096
#define NDIM 32
#define CDIM 256
#define DDIM 128
#define ROWS (BATCH * MDIM)        // 16384
#define LN_EPS 1e-5f
#define SCALE 0.08838834764831845f // 1/sqrt(128)

// ---------------- scratch (device globals, no allocation) ----------------
__device__ __align__(16) float g_Mraw[CDIM * CDIM]; // Wq @ Wk^T
__device__ __align__(16) float g_M3[CDIM * CDIM];   // qg[k] * Mraw[k][c] * kg[c]
__device__ __align__(16) float g_P[CDIM];           // kg[c] * (qb @ Mraw)[c]
__device__ __align__(16) float g_Q[CDIM];           // kg[c] * (qg @ Mraw)[c]
__device__ __align__(16) float g_bv2[CDIM];         // kg[c] * (Wk[c,:]·bq)
__device__ __align__(16) float g_rowvec[CDIM];      // mb[c] + u[c]
__device__ __align__(16) float g_e[CDIM];           // qg ⊙ rowvec
__device__ float g_const[1];                        // bq·(Wk^T kb + bk)
__device__ __align__(16) float g_w[ROWS * CDIM];    // per-row weight vectors
__device__ float g_Bc[ROWS];                        // per-row scalar bias

// ---------------- helpers ----------------
__device__ __forceinline__ float blockSum256(float v, float* s8) {
    #pragma unroll
    for (int o = 16; o; o >>= 1) v += __shfl_xor_sync(0xffffffffu, v, o);
    __syncthreads();
    if ((threadIdx.x & 31) == 0) s8[threadIdx.x >> 5] = v;
    __syncthreads();
    float tot = 0.f;
    #pragma unroll
    for (int i = 0; i < 8; i++) tot += s8[i];
    return tot;
}

#define FMA2(d, a, b) \
    asm("fma.rn.f32x2 %0, %1, %2, %0;" : "+l"(d) : "l"(a), "l"(b))
#define PACK2(out, lo, hi) \
    asm("mov.b64 %0, {%1, %2};" : "=l"(out) : "r"(__float_as_uint(lo)), "r"(__float_as_uint(hi)))
#define BAR_SYNC(id, cnt) \
    asm volatile("bar.sync %0, %1;" :: "r"(id), "r"(cnt) : "memory")

__device__ __forceinline__ float2 unpack2(unsigned long long v) {
    unsigned int lo, hi;
    asm("mov.b64 {%0, %1}, %2;" : "=r"(lo), "=r"(hi) : "l"(v));
    return make_float2(__uint_as_float(lo), __uint_as_float(hi));
}

// ---------------- K1a: Mraw = Wq(256x128) @ Wk^T(128x256), tiled ----------------
__global__ void prepA_kernel(const float* __restrict__ Wq, const float* __restrict__ Wk) {
    __shared__ float As[32][68];
    __shared__ float Bs[32][68];
    const int bm = blockIdx.y * 64;
    const int bn = blockIdx.x * 64;
    const int tid = threadIdx.x;
    const int tx = tid & 15, ty = tid >> 4;
    const int r = tid >> 2, dq = tid & 3;

    float acc[4][4];
    #pragma unroll
    for (int i = 0; i < 4; i++)
        #pragma unroll
        for (int j = 0; j < 4; j++) acc[i][j] = 0.f;

    for (int k0 = 0; k0 < DDIM; k0 += 32) {
        float4 a0 = *(const float4*)(Wq + (size_t)(bm + r) * DDIM + k0 + dq * 8);
        float4 a1 = *(const float4*)(Wq + (size_t)(bm + r) * DDIM + k0 + dq * 8 + 4);
        float4 b0 = *(const float4*)(Wk + (size_t)(bn + r) * DDIM + k0 + dq * 8);
        float4 b1 = *(const float4*)(Wk + (size_t)(bn + r) * DDIM + k0 + dq * 8 + 4);
        As[dq * 8 + 0][r] = a0.x; As[dq * 8 + 1][r] = a0.y;
        As[dq * 8 + 2][r] = a0.z; As[dq * 8 + 3][r] = a0.w;
        As[dq * 8 + 4][r] = a1.x; As[dq * 8 + 5][r] = a1.y;
        As[dq * 8 + 6][r] = a1.z; As[dq * 8 + 7][r] = a1.w;
        Bs[dq * 8 + 0][r] = b0.x; Bs[dq * 8 + 1][r] = b0.y;
        Bs[dq * 8 + 2][r] = b0.z; Bs[dq * 8 + 3][r] = b0.w;
        Bs[dq * 8 + 4][r] = b1.x; Bs[dq * 8 + 5][r] = b1.y;
        Bs[dq * 8 + 6][r] = b1.z; Bs[dq * 8 + 7][r] = b1.w;
        __syncthreads();
        #pragma unroll
        for (int k = 0; k < 32; k++) {
            float4 a = *(const float4*)&As[k][ty * 4];
            float4 b = *(const float4*)&Bs[k][tx * 4];
            float ai[4] = {a.x, a.y, a.z, a.w};
            float bj[4] = {b.x, b.y, b.z, b.w};
            #pragma unroll
            for (int i = 0; i < 4; i++)
                #pragma unroll
                for (int j = 0; j < 4; j++) acc[i][j] += ai[i] * bj[j];
        }
        __syncthreads();
    }
    #pragma unroll
    for (int i = 0; i < 4; i++)
        *(float4*)(g_Mraw + (size_t)(bm + ty * 4 + i) * CDIM + bn + tx * 4) =
            make_float4(acc[i][0], acc[i][1], acc[i][2], acc[i][3]);
}

// ---------------- K1b: derived vectors; blocks 0..255 per-row, 256: P/Q, 257: const ----------------
__global__ void prepB_kernel(const float* __restrict__ Wq, const float* __restrict__ Wk,
                             const float* __restrict__ bq, const float* __restrict__ bk,
                             const float* __restrict__ kg, const float* __restrict__ kb,
                             const float* __restrict__ qg, const float* __restrict__ qb) {
    const int c = blockIdx.x;
    const int t = threadIdx.x;
    __shared__ float s8[8];
    __shared__ float sA[CDIM], sB[CDIM];

    if (c < CDIM) {
        float mraw = g_Mraw[(size_t)c * CDIM + t];
        g_M3[(size_t)c * CDIM + t] = mraw * kg[t] * qg[c];
        float mb = blockSum256(mraw * kb[t], s8);
        float u  = blockSum256(t < DDIM ? Wq[(size_t)c * DDIM + t] * bk[t] : 0.f, s8);
        float bv = blockSum256(t < DDIM ? Wk[(size_t)c * DDIM + t] * bq[t] : 0.f, s8);
        if (t == 0) {
            float rv = mb + u;
            g_rowvec[c] = rv;
            g_e[c] = qg[c] * rv;
            g_bv2[c] = bv * kg[c];
        }
    } else if (c == CDIM) {
        sA[t] = qb[t];
        sB[t] = qg[t];
        __syncthreads();
        float accP = 0.f, accQ = 0.f;
        for (int k = 0; k < CDIM; k++) {
            float m = g_Mraw[(size_t)k * CDIM + t];   // coalesced over t
            accP += sA[k] * m;
            accQ += sB[k] * m;
        }
        float kgt = kg[t];
        g_P[t] = kgt * accP;
        g_Q[t] = kgt * accQ;
    } else {
        float acc = 0.f;
        if (t < DDIM) {
            for (int c2 = 0; c2 < CDIM; c2++) acc += Wk[(size_t)c2 * DDIM + t] * kb[c2];
            acc = (acc + bk[t]) * bq[t];
        }
        float tot = blockSum256(acc, s8);
        if (t == 0) g_const[0] = tot;
    }
}

// ---------------- K2: GEMM acc = x @ M3 ; 128x128 tile, 8x8/thread, BK=16, double-buffered ----------------
__global__ void __launch_bounds__(256, 2)
gemm_kernel(const float* __restrict__ x, const float* __restrict__ qb) {
    __shared__ __align__(16) float As[2][16][132];   // [buf][k][m]
    __shared__ __align__(16) float Bs[2][16][132];   // [buf][k][n]
    __shared__ float s_mu[128], s_rs[128];
    __shared__ __align__(16) float s_e[CDIM];
    __shared__ float s8[8];

    const int bm = blockIdx.y * 128;
    const int bn = blockIdx.x * 128;
    const int tid = threadIdx.x;

    // ---- phase 0: e into smem; E, F block scalars ----
    float ev = g_e[tid];
    s_e[tid] = ev;
    float E = blockSum256(ev, s8);
    float F = blockSum256(qb[tid] * g_rowvec[tid], s8);

    // ---- phase 1: per-row stats, 2 threads per row (also warms x tile in L1) ----
    {
        const int ar = tid >> 1, half = tid & 1;
        const float* xr = x + (size_t)(bm + ar) * CDIM + half * 4;
        float s1 = 0.f, s2 = 0.f, s3 = 0.f;
        #pragma unroll
        for (int j = 0; j < 32; j++) {
            float4 v = *(const float4*)(xr + j * 8);
            const float* ep = s_e + half * 4 + j * 8;
            s1 += v.x + v.y + v.z + v.w;
            s2 += v.x * v.x + v.y * v.y + v.z * v.z + v.w * v.w;
            s3 += v.x * ep[0] + v.y * ep[1] + v.z * ep[2] + v.w * ep[3];
        }
        s1 += __shfl_xor_sync(0xffffffffu, s1, 1);
        s2 += __shfl_xor_sync(0xffffffffu, s2, 1);
        s3 += __shfl_xor_sync(0xffffffffu, s3, 1);
        if (half == 0) {
            float mu = s1 * (1.f / CDIM);
            float var = s2 * (1.f / CDIM) - mu * mu;
            float rs = rsqrtf(var + LN_EPS);
            s_mu[ar] = mu;
            s_rs[ar] = rs;
            if (blockIdx.x == 0)
                g_Bc[bm + ar] = rs * (s3 - mu * E) + F + g_const[0];
        }
    }
    __syncthreads();

    // ---- main loop: raw x @ M3, BK=16, double-buffered smem, 8x8 per thread ----
    const int ar = tid >> 1, aq = tid & 1;          // A staging: row, k-octet
    const int bkr = tid >> 4, bcq = tid & 15;       // B staging: k-row, col-octet
    const int tx = tid & 15, ty = tid >> 4;         // compute mapping

    const float* xpa = x + (size_t)(bm + ar) * CDIM + aq * 8;
    const float* bp  = g_M3 + (size_t)bkr * CDIM + bn + bcq * 8;

    unsigned long long acc[8][4];
    #pragma unroll
    for (int i = 0; i < 8; i++)
        #pragma unroll
        for (int j = 0; j < 4; j++) acc[i][j] = 0ull;

    // prologue: stage slab 0 into buffer 0
    {
        float4 a0 = *(const float4*)(xpa);
        float4 a1 = *(const float4*)(xpa + 4);
        float4 b0 = *(const float4*)(bp);
        float4 b1 = *(const float4*)(bp + 4);
        As[0][aq * 8 + 0][ar] = a0.x; As[0][aq * 8 + 1][ar] = a0.y;
        As[0][aq * 8 + 2][ar] = a0.z; As[0][aq * 8 + 3][ar] = a0.w;
        As[0][aq * 8 + 4][ar] = a1.x; As[0][aq * 8 + 5][ar] = a1.y;
        As[0][aq * 8 + 6][ar] = a1.z; As[0][aq * 8 + 7][ar] = a1.w;
        *(float4*)&Bs[0][bkr][bcq * 8]     = b0;
        *(float4*)&Bs[0][bkr][bcq * 8 + 4] = b1;
    }
    __syncthreads();

    #pragma unroll 1
    for (int k0 = 0; k0 < CDIM; k0 += 16) {
        const int b = (k0 >> 4) & 1;
        const bool has_next = (k0 + 16 < CDIM);

        // issue next slab's global loads early (latency hides under compute)
        float4 a0, a1, b0, b1;
        if (has_next) {
            a0 = *(const float4*)(xpa + k0 + 16);
            a1 = *(const float4*)(xpa + k0 + 20);
            b0 = *(const float4*)(bp + (size_t)(k0 + 16) * CDIM);
            b1 = *(const float4*)(bp + (size_t)(k0 + 16) * CDIM + 4);
        }

        // compute from buffer b
        #pragma unroll
        for (int k = 0; k < 16; k++) {
            float4 av0 = *(const float4*)&As[b][k][ty * 8];        // broadcast
            float4 av1 = *(const float4*)&As[b][k][ty * 8 + 4];    // broadcast
            ulonglong2 q0 = *(const ulonglong2*)&Bs[b][k][tx * 4];
            ulonglong2 q1 = *(const ulonglong2*)&Bs[b][k][64 + tx * 4];
            unsigned long long bb0 = q0.x, bb1 = q0.y, bb2 = q1.x, bb3 = q1.y;
            float avv[8] = {av0.x, av0.y, av0.z, av0.w, av1.x, av1.y, av1.z, av1.w};
            #pragma unroll
            for (int i = 0; i < 8; i++) {
                unsigned long long ad;
                PACK2(ad, avv[i], avv[i]);
                FMA2(acc[i][0], ad, bb0);
                FMA2(acc[i][1], ad, bb1);
                FMA2(acc[i][2], ad, bb2);
                FMA2(acc[i][3], ad, bb3);
            }
        }

        // stage next slab into the other buffer
        if (has_next) {
            const int nb = b ^ 1;
            As[nb][aq * 8 + 0][ar] = a0.x; As[nb][aq * 8 + 1][ar] = a0.y;
            As[nb][aq * 8 + 2][ar] = a0.z; As[nb][aq * 8 + 3][ar] = a0.w;
            As[nb][aq * 8 + 4][ar] = a1.x; As[nb][aq * 8 + 5][ar] = a1.y;
            As[nb][aq * 8 + 6][ar] = a1.z; As[nb][aq * 8 + 7][ar] = a1.w;
            *(float4*)&Bs[nb][bkr][bcq * 8]     = b0;
            *(float4*)&Bs[nb][bkr][bcq * 8 + 4] = b1;
            __syncthreads();
        }
    }

    // ---- epilogue: w = rs*acc + P - rs*mu*Q + bv2 ----
    float4 P0 = *(const float4*)(g_P + bn + tx * 4);
    float4 P1 = *(const float4*)(g_P + bn + 64 + tx * 4);
    float4 Q0 = *(const float4*)(g_Q + bn + tx * 4);
    float4 Q1 = *(const float4*)(g_Q + bn + 64 + tx * 4);
    float4 V0 = *(const float4*)(g_bv2 + bn + tx * 4);
    float4 V1 = *(const float4*)(g_bv2 + bn + 64 + tx * 4);
    #pragma unroll
    for (int i = 0; i < 8; i++) {
        const int rl = ty * 8 + i;
        const float rs = s_rs[rl];
        const float rm = rs * s_mu[rl];
        const int row = bm + rl;
        float2 p0 = unpack2(acc[i][0]);
        float2 p1 = unpack2(acc[i][1]);
        float2 p2 = unpack2(acc[i][2]);
        float2 p3 = unpack2(acc[i][3]);
        *(float4*)(g_w + (size_t)row * CDIM + bn + tx * 4) = make_float4(
            fmaf(rs, p0.x, P0.x - rm * Q0.x + V0.x),
            fmaf(rs, p0.y, P0.y - rm * Q0.y + V0.y),
            fmaf(rs, p1.x, P0.z - rm * Q0.z + V0.z),
            fmaf(rs, p1.y, P0.w - rm * Q0.w + V0.w));
        *(float4*)(g_w + (size_t)row * CDIM + bn + 64 + tx * 4) = make_float4(
            fmaf(rs, p2.x, P1.x - rm * Q1.x + V1.x),
            fmaf(rs, p2.y, P1.y - rm * Q1.y + V1.y),
            fmaf(rs, p3.x, P1.z - rm * Q1.z + V1.z),
            fmaf(rs, p3.y, P1.w - rm * Q1.w + V1.w));
    }
}

// ---------------- K3: attention, 2 independent rows per 512-thread block ----------------
// Halves (threads 0-255 / 256-511) share NOTHING; each uses its own named barrier.
__global__ void __launch_bounds__(512)
attn_kernel(const float* __restrict__ y, const float* __restrict__ z,
            float* __restrict__ out) {
    __shared__ __align__(16) float sw[2][CDIM];
    __shared__ float s8[2][8];
    __shared__ float sdot[2][NDIM];

    const int tid = threadIdx.x;
    const int half = tid >> 8;         // 0 or 1 (warp-uniform)
    const int t = tid & 255;
    const int row = blockIdx.x * 2 + half;
    const int barid = 1 + half;

    // issue all y loads first — latency hides under the w reduction below
    const int n = t >> 3, t8 = t & 7;
    const float* yr = y + ((size_t)row * NDIM + n) * CDIM;
    float4 yv[8];
    #pragma unroll
    for (int j = 0; j < 8; j++)
        yv[j] = __ldcs((const float4*)(yr + j * 32 + t8 * 4));

    // w into smem + half-wide sum G
    float wv = g_w[(size_t)row * CDIM + t];
    sw[half][t] = wv;
    float G;
    {
        float v = wv;
        #pragma unroll
        for (int o = 16; o; o >>= 1) v += __shfl_xor_sync(0xffffffffu, v, o);
        if ((t & 31) == 0) s8[half][t >> 5] = v;
        BAR_SYNC(barid, 256);
        G = 0.f;
        #pragma unroll
        for (int i = 0; i < 8; i++) G += s8[half][i];
    }

    float S1 = 0.f, S2 = 0.f, S3 = 0.f;
    #pragma unroll
    for (int j = 0; j < 8; j++) {
        float4 w4 = *(const float4*)(sw[half] + j * 32 + t8 * 4);
        S1 += yv[j].x + yv[j].y + yv[j].z + yv[j].w;
        S2 += yv[j].x * yv[j].x + yv[j].y * yv[j].y + yv[j].z * yv[j].z + yv[j].w * yv[j].w;
        S3 += yv[j].x * w4.x + yv[j].y * w4.y + yv[j].z * w4.z + yv[j].w * w4.w;
    }
    #pragma unroll
    for (int o = 4; o; o >>= 1) {
        S1 += __shfl_down_sync(0xffffffffu, S1, o);
        S2 += __shfl_down_sync(0xffffffffu, S2, o);
        S3 += __shfl_down_sync(0xffffffffu, S3, o);
    }
    if (t8 == 0) {
        float mu = S1 * (1.f / CDIM);
        float var = S2 * (1.f / CDIM) - mu * mu;
        float rs = rsqrtf(var + LN_EPS);
        sdot[half][n] = SCALE * (rs * (S3 - mu * G) + g_Bc[row]);
    }
    BAR_SYNC(barid, 256);
    if (t < NDIM) {
        float v = sdot[half][t];
        float m = v;
        #pragma unroll
        for (int o = 16; o; o >>= 1) m = fmaxf(m, __shfl_xor_sync(0xffffffffu, m, o));
        float e = expf(v - m);
        float zb = z[(size_t)row * NDIM + t];
        float se = e, sez = e * zb;
        #pragma unroll
        for (int o = 16; o; o >>= 1) {
            se += __shfl_xor_sync(0xffffffffu, se, o);
            sez += __shfl_xor_sync(0xffffffffu, sez, o);
        }
        if (t == 0) out[row] = sez / se;
    }
}

// ---------------- launch ----------------
extern "C" void kernel_launch(void* const* d_in, const int* in_sizes, int n_in,
                              void* d_out, int out_size) {
    const float* x  = (const float*)d_in[0];
    const float* y  = (const float*)d_in[1];
    const float* z  = (const float*)d_in[2];
    const float* qg = (const float*)d_in[3];
    const float* qb = (const float*)d_in[4];
    const float* Wq = (const float*)d_in[5];
    const float* bq = (const float*)d_in[6];
    const float* kg = (const float*)d_in[7];
    const float* kb = (const float*)d_in[8];
    const float* Wk = (const float*)d_in[9];
    const float* bk = (const float*)d_in[10];
    float* out = (float*)d_out;

    prepA_kernel<<<dim3(4, 4), 256>>>(Wq, Wk);
    prepB_kernel<<<CDIM + 2, 256>>>(Wq, Wk, bq, bk, kg, kb, qg, qb);
    gemm_kernel<<<dim3(2, ROWS / 128), 256>>>(x, qb);
    attn_kernel<<<ROWS / 2, 512>>>(y, z, out);
}

// round 15
// speedup vs baseline: 1.0403x; 1.0403x over previous
#include <cuda_runtime.h>
#include <cuda_bf16.h>
#include <cstdint>

// Problem constants (fixed by setup_inputs)
#define BATCH 4
#define MDIM 4096
#define NDIM 32
#define CDIM 256
#define DDIM 128
#define ROWS (BATCH * MDIM)        // 16384
#define LN_EPS 1e-5f
#define SCALE 0.08838834764831845f // 1/sqrt(128)

// ---------------- scratch (device globals, no allocation) ----------------
__device__ __align__(16) float g_Mraw[CDIM * CDIM]; // Wq @ Wk^T
__device__ __align__(16) float g_M3[CDIM * CDIM];   // qg[k] * Mraw[k][c] * kg[c]
__device__ __align__(16) float g_P[CDIM];           // kg[c] * (qb @ Mraw)[c]
__device__ __align__(16) float g_Q[CDIM];           // kg[c] * (qg @ Mraw)[c]
__device__ __align__(16) float g_bv2[CDIM];         // kg[c] * (Wk[c,:]·bq)
__device__ __align__(16) float g_rowvec[CDIM];      // mb[c] + u[c]
__device__ __align__(16) float g_e[CDIM];           // qg ⊙ rowvec
__device__ float g_const[1];                        // bq·(Wk^T kb + bk)
__device__ __align__(16) float g_w[ROWS * CDIM];    // per-row weight vectors
__device__ float g_Bc[ROWS];                        // per-row scalar bias

// ---------------- helpers ----------------
__device__ __forceinline__ float blockSum256(float v, float* s8) {
    #pragma unroll
    for (int o = 16; o; o >>= 1) v += __shfl_xor_sync(0xffffffffu, v, o);
    __syncthreads();
    if ((threadIdx.x & 31) == 0) s8[threadIdx.x >> 5] = v;
    __syncthreads();
    float tot = 0.f;
    #pragma unroll
    for (int i = 0; i < 8; i++) tot += s8[i];
    return tot;
}

#define FMA2(d, a, b) \
    asm("fma.rn.f32x2 %0, %1, %2, %0;" : "+l"(d) : "l"(a), "l"(b))
#define PACK2(out, lo, hi) \
    asm("mov.b64 %0, {%1, %2};" : "=l"(out) : "r"(__float_as_uint(lo)), "r"(__float_as_uint(hi)))

__device__ __forceinline__ float2 unpack2(unsigned long long v) {
    unsigned int lo, hi;
    asm("mov.b64 {%0, %1}, %2;" : "=r"(lo), "=r"(hi) : "l"(v));
    return make_float2(__uint_as_float(lo), __uint_as_float(hi));
}

// ---------------- K1a: Mraw = Wq(256x128) @ Wk^T(128x256), tiled ----------------
__global__ void prepA_kernel(const float* __restrict__ Wq, const float* __restrict__ Wk) {
    __shared__ float As[32][68];
    __shared__ float Bs[32][68];
    const int bm = blockIdx.y * 64;
    const int bn = blockIdx.x * 64;
    const int tid = threadIdx.x;
    const int tx = tid & 15, ty = tid >> 4;
    const int r = tid >> 2, dq = tid & 3;

    float acc[4][4];
    #pragma unroll
    for (int i = 0; i < 4; i++)
        #pragma unroll
        for (int j = 0; j < 4; j++) acc[i][j] = 0.f;

    for (int k0 = 0; k0 < DDIM; k0 += 32) {
        float4 a0 = *(const float4*)(Wq + (size_t)(bm + r) * DDIM + k0 + dq * 8);
        float4 a1 = *(const float4*)(Wq + (size_t)(bm + r) * DDIM + k0 + dq * 8 + 4);
        float4 b0 = *(const float4*)(Wk + (size_t)(bn + r) * DDIM + k0 + dq * 8);
        float4 b1 = *(const float4*)(Wk + (size_t)(bn + r) * DDIM + k0 + dq * 8 + 4);
        As[dq * 8 + 0][r] = a0.x; As[dq * 8 + 1][r] = a0.y;
        As[dq * 8 + 2][r] = a0.z; As[dq * 8 + 3][r] = a0.w;
        As[dq * 8 + 4][r] = a1.x; As[dq * 8 + 5][r] = a1.y;
        As[dq * 8 + 6][r] = a1.z; As[dq * 8 + 7][r] = a1.w;
        Bs[dq * 8 + 0][r] = b0.x; Bs[dq * 8 + 1][r] = b0.y;
        Bs[dq * 8 + 2][r] = b0.z; Bs[dq * 8 + 3][r] = b0.w;
        Bs[dq * 8 + 4][r] = b1.x; Bs[dq * 8 + 5][r] = b1.y;
        Bs[dq * 8 + 6][r] = b1.z; Bs[dq * 8 + 7][r] = b1.w;
        __syncthreads();
        #pragma unroll
        for (int k = 0; k < 32; k++) {
            float4 a = *(const float4*)&As[k][ty * 4];
            float4 b = *(const float4*)&Bs[k][tx * 4];
            float ai[4] = {a.x, a.y, a.z, a.w};
            float bj[4] = {b.x, b.y, b.z, b.w};
            #pragma unroll
            for (int i = 0; i < 4; i++)
                #pragma unroll
                for (int j = 0; j < 4; j++) acc[i][j] += ai[i] * bj[j];
        }
        __syncthreads();
    }
    #pragma unroll
    for (int i = 0; i < 4; i++)
        *(float4*)(g_Mraw + (size_t)(bm + ty * 4 + i) * CDIM + bn + tx * 4) =
            make_float4(acc[i][0], acc[i][1], acc[i][2], acc[i][3]);
}

// ---------------- K1b: derived vectors; blocks 0..255 per-row, 256: P/Q, 257: const ----------------
__global__ void prepB_kernel(const float* __restrict__ Wq, const float* __restrict__ Wk,
                             const float* __restrict__ bq, const float* __restrict__ bk,
                             const float* __restrict__ kg, const float* __restrict__ kb,
                             const float* __restrict__ qg, const float* __restrict__ qb) {
    const int c = blockIdx.x;
    const int t = threadIdx.x;
    __shared__ float s8[8];
    __shared__ float sA[CDIM], sB[CDIM];

    if (c < CDIM) {
        float mraw = g_Mraw[(size_t)c * CDIM + t];
        g_M3[(size_t)c * CDIM + t] = mraw * kg[t] * qg[c];
        float mb = blockSum256(mraw * kb[t], s8);
        float u  = blockSum256(t < DDIM ? Wq[(size_t)c * DDIM + t] * bk[t] : 0.f, s8);
        float bv = blockSum256(t < DDIM ? Wk[(size_t)c * DDIM + t] * bq[t] : 0.f, s8);
        if (t == 0) {
            float rv = mb + u;
            g_rowvec[c] = rv;
            g_e[c] = qg[c] * rv;
            g_bv2[c] = bv * kg[c];
        }
    } else if (c == CDIM) {
        sA[t] = qb[t];
        sB[t] = qg[t];
        __syncthreads();
        float accP = 0.f, accQ = 0.f;
        for (int k = 0; k < CDIM; k++) {
            float m = g_Mraw[(size_t)k * CDIM + t];   // coalesced over t
            accP += sA[k] * m;
            accQ += sB[k] * m;
        }
        float kgt = kg[t];
        g_P[t] = kgt * accP;
        g_Q[t] = kgt * accQ;
    } else {
        float acc = 0.f;
        if (t < DDIM) {
            for (int c2 = 0; c2 < CDIM; c2++) acc += Wk[(size_t)c2 * DDIM + t] * kb[c2];
            acc = (acc + bk[t]) * bq[t];
        }
        float tot = blockSum256(acc, s8);
        if (t == 0) g_const[0] = tot;
    }
}

// ---------------- K2: GEMM acc = x @ M3 ; 128x128 tile, 8x8/thread, BK=16 ----------------
// Stats (mu, rs, Bc) accumulated IN the A-staging path; LN applied in epilogue.
__global__ void __launch_bounds__(256, 2)
gemm_kernel(const float* __restrict__ x, const float* __restrict__ qb) {
    __shared__ __align__(16) float As[2][16][132];   // [buf][k][m]
    __shared__ __align__(16) float Bs[2][16][132];   // [buf][k][n]
    __shared__ float s_mu[128], s_rs[128];
    __shared__ __align__(16) float s_e[CDIM];
    __shared__ float s8[8];

    const int bm = blockIdx.y * 128;
    const int bn = blockIdx.x * 128;
    const int tid = threadIdx.x;

    // ---- phase 0: e into smem; E, F block scalars ----
    float ev = g_e[tid];
    s_e[tid] = ev;
    float E = blockSum256(ev, s8);
    float F = blockSum256(qb[tid] * g_rowvec[tid], s8);

    // ---- main loop: raw x @ M3, BK=16, double-buffered; stats fused into staging ----
    const int ar = tid >> 1, aq = tid & 1;          // A staging: row, k-octet
    const int bkr = tid >> 4, bcq = tid & 15;       // B staging: k-row, col-octet
    const int tx = tid & 15, ty = tid >> 4;         // compute mapping

    const float* xpa = x + (size_t)(bm + ar) * CDIM + aq * 8;
    const float* bp  = g_M3 + (size_t)bkr * CDIM + bn + bcq * 8;

    unsigned long long acc[8][4];
    #pragma unroll
    for (int i = 0; i < 8; i++)
        #pragma unroll
        for (int j = 0; j < 4; j++) acc[i][j] = 0ull;

    float s1 = 0.f, s2 = 0.f, s3 = 0.f;   // per-(row, aq-half) stats accumulators

    // prologue: stage slab 0 into buffer 0 (+stats)
    {
        float4 a0 = *(const float4*)(xpa);
        float4 a1 = *(const float4*)(xpa + 4);
        float4 e0 = *(const float4*)(s_e + aq * 8);
        float4 e1 = *(const float4*)(s_e + aq * 8 + 4);
        s1 += a0.x + a0.y + a0.z + a0.w + a1.x + a1.y + a1.z + a1.w;
        s2 += a0.x*a0.x + a0.y*a0.y + a0.z*a0.z + a0.w*a0.w
            + a1.x*a1.x + a1.y*a1.y + a1.z*a1.z + a1.w*a1.w;
        s3 += a0.x*e0.x + a0.y*e0.y + a0.z*e0.z + a0.w*e0.w
            + a1.x*e1.x + a1.y*e1.y + a1.z*e1.z + a1.w*e1.w;
        As[0][aq * 8 + 0][ar] = a0.x; As[0][aq * 8 + 1][ar] = a0.y;
        As[0][aq * 8 + 2][ar] = a0.z; As[0][aq * 8 + 3][ar] = a0.w;
        As[0][aq * 8 + 4][ar] = a1.x; As[0][aq * 8 + 5][ar] = a1.y;
        As[0][aq * 8 + 6][ar] = a1.z; As[0][aq * 8 + 7][ar] = a1.w;
        float4 b0 = *(const float4*)(bp);
        float4 b1 = *(const float4*)(bp + 4);
        *(float4*)&Bs[0][bkr][bcq * 8]     = b0;
        *(float4*)&Bs[0][bkr][bcq * 8 + 4] = b1;
    }
    __syncthreads();

    #pragma unroll 1
    for (int k0 = 0; k0 < CDIM; k0 += 16) {
        const int b = (k0 >> 4) & 1;
        const bool has_next = (k0 + 16 < CDIM);

        // issue next slab's global loads early (latency hides under compute)
        float4 a0, a1, b0, b1;
        if (has_next) {
            a0 = *(const float4*)(xpa + k0 + 16);
            a1 = *(const float4*)(xpa + k0 + 20);
            b0 = *(const float4*)(bp + (size_t)(k0 + 16) * CDIM);
            b1 = *(const float4*)(bp + (size_t)(k0 + 16) * CDIM + 4);
        }

        // compute from buffer b
        #pragma unroll
        for (int k = 0; k < 16; k++) {
            float4 av0 = *(const float4*)&As[b][k][ty * 8];        // broadcast
            float4 av1 = *(const float4*)&As[b][k][ty * 8 + 4];    // broadcast
            ulonglong2 q0 = *(const ulonglong2*)&Bs[b][k][tx * 4];
            ulonglong2 q1 = *(const ulonglong2*)&Bs[b][k][64 + tx * 4];
            unsigned long long bb0 = q0.x, bb1 = q0.y, bb2 = q1.x, bb3 = q1.y;
            float avv[8] = {av0.x, av0.y, av0.z, av0.w, av1.x, av1.y, av1.z, av1.w};
            #pragma unroll
            for (int i = 0; i < 8; i++) {
                unsigned long long ad;
                PACK2(ad, avv[i], avv[i]);
                FMA2(acc[i][0], ad, bb0);
                FMA2(acc[i][1], ad, bb1);
                FMA2(acc[i][2], ad, bb2);
                FMA2(acc[i][3], ad, bb3);
            }
        }

        // stage next slab into the other buffer (+stats)
        if (has_next) {
            const int nb = b ^ 1;
            float4 e0 = *(const float4*)(s_e + k0 + 16 + aq * 8);
            float4 e1 = *(const float4*)(s_e + k0 + 16 + aq * 8 + 4);
            s1 += a0.x + a0.y + a0.z + a0.w + a1.x + a1.y + a1.z + a1.w;
            s2 += a0.x*a0.x + a0.y*a0.y + a0.z*a0.z + a0.w*a0.w
                + a1.x*a1.x + a1.y*a1.y + a1.z*a1.z + a1.w*a1.w;
            s3 += a0.x*e0.x + a0.y*e0.y + a0.z*e0.z + a0.w*e0.w
                + a1.x*e1.x + a1.y*e1.y + a1.z*e1.z + a1.w*e1.w;
            As[nb][aq * 8 + 0][ar] = a0.x; As[nb][aq * 8 + 1][ar] = a0.y;
            As[nb][aq * 8 + 2][ar] = a0.z; As[nb][aq * 8 + 3][ar] = a0.w;
            As[nb][aq * 8 + 4][ar] = a1.x; As[nb][aq * 8 + 5][ar] = a1.y;
            As[nb][aq * 8 + 6][ar] = a1.z; As[nb][aq * 8 + 7][ar] = a1.w;
            *(float4*)&Bs[nb][bkr][bcq * 8]     = b0;
            *(float4*)&Bs[nb][bkr][bcq * 8 + 4] = b1;
            __syncthreads();
        }
    }

    // ---- finalize stats: reduce the two aq-halves (adjacent lanes) ----
    s1 += __shfl_xor_sync(0xffffffffu, s1, 1);
    s2 += __shfl_xor_sync(0xffffffffu, s2, 1);
    s3 += __shfl_xor_sync(0xffffffffu, s3, 1);
    if (aq == 0) {
        float mu = s1 * (1.f / CDIM);
        float var = s2 * (1.f / CDIM) - mu * mu;
        float rs = rsqrtf(var + LN_EPS);
        s_mu[ar] = mu;
        s_rs[ar] = rs;
        if (blockIdx.x == 0)
            g_Bc[bm + ar] = rs * (s3 - mu * E) + F + g_const[0];
    }
    __syncthreads();

    // ---- epilogue: w = rs*acc + P - rs*mu*Q + bv2 ----
    float4 P0 = *(const float4*)(g_P + bn + tx * 4);
    float4 P1 = *(const float4*)(g_P + bn + 64 + tx * 4);
    float4 Q0 = *(const float4*)(g_Q + bn + tx * 4);
    float4 Q1 = *(const float4*)(g_Q + bn + 64 + tx * 4);
    float4 V0 = *(const float4*)(g_bv2 + bn + tx * 4);
    float4 V1 = *(const float4*)(g_bv2 + bn + 64 + tx * 4);
    #pragma unroll
    for (int i = 0; i < 8; i++) {
        const int rl = ty * 8 + i;
        const float rs = s_rs[rl];
        const float rm = rs * s_mu[rl];
        const int row = bm + rl;
        float2 p0 = unpack2(acc[i][0]);
        float2 p1 = unpack2(acc[i][1]);
        float2 p2 = unpack2(acc[i][2]);
        float2 p3 = unpack2(acc[i][3]);
        *(float4*)(g_w + (size_t)row * CDIM + bn + tx * 4) = make_float4(
            fmaf(rs, p0.x, P0.x - rm * Q0.x + V0.x),
            fmaf(rs, p0.y, P0.y - rm * Q0.y + V0.y),
            fmaf(rs, p1.x, P0.z - rm * Q0.z + V0.z),
            fmaf(rs, p1.y, P0.w - rm * Q0.w + V0.w));
        *(float4*)(g_w + (size_t)row * CDIM + bn + 64 + tx * 4) = make_float4(
            fmaf(rs, p2.x, P1.x - rm * Q1.x + V1.x),
            fmaf(rs, p2.y, P1.y - rm * Q1.y + V1.y),
            fmaf(rs, p3.x, P1.z - rm * Q1.z + V1.z),
            fmaf(rs, p3.y, P1.w - rm * Q1.w + V1.w));
    }
}

// ---------------- K3: main streaming pass over y + softmax + z-sum (R13 version) ----------------
__global__ void attn_kernel(const float* __restrict__ y, const float* __restrict__ z,
                            float* __restrict__ out) {
    const int row = blockIdx.x;    // b*M + m
    const int tid = threadIdx.x;   // 256 threads
    __shared__ __align__(16) float sw[CDIM];
    __shared__ float s8[8];
    __shared__ float sdot[NDIM];

    // issue all y loads first — latency hides under the w reduction below
    const int n = tid >> 3, t8 = tid & 7;
    const float* yr = y + ((size_t)row * NDIM + n) * CDIM;
    float4 yv[8];
    #pragma unroll
    for (int j = 0; j < 8; j++)
        yv[j] = __ldcs((const float4*)(yr + j * 32 + t8 * 4));

    float wv = g_w[(size_t)row * CDIM + tid];
    sw[tid] = wv;
    float G = blockSum256(wv, s8);   // includes syncthreads -> sw visible

    float S1 = 0.f, S2 = 0.f, S3 = 0.f;
    #pragma unroll
    for (int j = 0; j < 8; j++) {
        float4 w4 = *(const float4*)(sw + j * 32 + t8 * 4);
        S1 += yv[j].x + yv[j].y + yv[j].z + yv[j].w;
        S2 += yv[j].x * yv[j].x + yv[j].y * yv[j].y + yv[j].z * yv[j].z + yv[j].w * yv[j].w;
        S3 += yv[j].x * w4.x + yv[j].y * w4.y + yv[j].z * w4.z + yv[j].w * w4.w;
    }
    #pragma unroll
    for (int o = 4; o; o >>= 1) {
        S1 += __shfl_down_sync(0xffffffffu, S1, o);
        S2 += __shfl_down_sync(0xffffffffu, S2, o);
        S3 += __shfl_down_sync(0xffffffffu, S3, o);
    }
    if (t8 == 0) {
        float mu = S1 * (1.f / CDIM);
        float var = S2 * (1.f / CDIM) - mu * mu;
        float rs = rsqrtf(var + LN_EPS);
        sdot[n] = SCALE * (rs * (S3 - mu * G) + g_Bc[row]);
    }
    __syncthreads();
    if (tid < NDIM) {
        float v = sdot[tid];
        float m = v;
        #pragma unroll
        for (int o = 16; o; o >>= 1) m = fmaxf(m, __shfl_xor_sync(0xffffffffu, m, o));
        float e = expf(v - m);
        float zb = z[(size_t)row * NDIM + tid];
        float se = e, sez = e * zb;
        #pragma unroll
        for (int o = 16; o; o >>= 1) {
            se += __shfl_xor_sync(0xffffffffu, se, o);
            sez += __shfl_xor_sync(0xffffffffu, sez, o);
        }
        if (tid == 0) out[row] = sez / se;
    }
}

// ---------------- launch ----------------
extern "C" void kernel_launch(void* const* d_in, const int* in_sizes, int n_in,
                              void* d_out, int out_size) {
    const float* x  = (const float*)d_in[0];
    const float* y  = (const float*)d_in[1];
    const float* z  = (const float*)d_in[2];
    const float* qg = (const float*)d_in[3];
    const float* qb = (const float*)d_in[4];
    const float* Wq = (const float*)d_in[5];
    const float* bq = (const float*)d_in[6];
    const float* kg = (const float*)d_in[7];
    const float* kb = (const float*)d_in[8];
    const float* Wk = (const float*)d_in[9];
    const float* bk = (const float*)d_in[10];
    float* out = (float*)d_out;

    prepA_kernel<<<dim3(4, 4), 256>>>(Wq, Wk);
    prepB_kernel<<<CDIM + 2, 256>>>(Wq, Wk, bq, bk, kg, kb, qg, qb);
    gemm_kernel<<<dim3(2, ROWS / 128), 256>>>(x, qb);
    attn_kernel<<<ROWS, 256>>>(y, z, out);
}